// round 15
// baseline (speedup 1.0000x reference)
#include <cuda_runtime.h>
#include <math.h>

#define NN 100000
#define FD 512
#define HD 16
#define CD 40
#define EMAX 3400000
#define NB_NODE 391   // ceil(NN/256)

// ---------------- scratch (device globals; no allocation allowed) ----------
__device__ int g_is64;
__device__ __align__(16) int    g_cnt   [NN];     // in-degree (excl self)
__device__ __align__(16) int    g_start [NN];     // CSR row start
__device__ __align__(16) int    g_cursor[NN];
__device__ __align__(16) int    g_bsum  [512];
__device__ __align__(16) int    g_csr [EMAX];     // src ids grouped by dst
__device__ __align__(16) float  g_dinv[NN];
__device__ __align__(16) float4 g_h1s [NN * 4];   // (x@W1)*dinv
__device__ __align__(16) float4 g_ts  [NN * 4];   // relu(out1)*dinv
__device__ __align__(16) float4 g_acc2[NN * 4];   // layer-2 aggregate (raw)

// packed fp32x2 helpers (Blackwell f32x2 — PTX only)
__device__ __forceinline__ unsigned long long pk2(float a, float b) {
    unsigned long long r;
    asm("mov.b64 %0, {%1, %2};" : "=l"(r) : "f"(a), "f"(b));
    return r;
}
__device__ __forceinline__ void fma2(unsigned long long& d,
                                     unsigned long long a, unsigned long long b) {
    asm("fma.rn.f32x2 %0, %1, %2, %0;" : "+l"(d) : "l"(a), "l"(b));
}
__device__ __forceinline__ void add2(unsigned long long& d, unsigned long long a) {
    asm("add.rn.f32x2 %0, %0, %1;" : "+l"(d) : "l"(a));
}
__device__ __forceinline__ float unpk_sum(unsigned long long v) {
    float lo, hi;
    asm("mov.b64 {%0, %1}, %2;" : "=f"(lo), "=f"(hi) : "l"(v));
    return lo + hi;
}

// ---------------- K: detect edge-index dtype --------------------------------
__global__ void k_detect(const int* __restrict__ buf) {
    int nz = 0;
    for (int i = threadIdx.x; i < 256; i += 32) nz |= buf[2 * i + 1];
#pragma unroll
    for (int o = 16; o; o >>= 1) nz |= __shfl_xor_sync(0xffffffffu, nz, o);
    if (threadIdx.x == 0) g_is64 = (nz == 0) ? 1 : 0;
}

// ---------------- K: zero counters ------------------------------------------
__global__ void k_init() {
    int i = blockIdx.x * blockDim.x + threadIdx.x;
    if (i < NN) { g_cnt[i] = 0; g_cursor[i] = 0; }
}

// ---------------- K: degree histogram (decode dst in place) -----------------
__global__ void k_count(const void* __restrict__ buf, int E) {
    int e = blockIdx.x * blockDim.x + threadIdx.x;
    if (e >= E) return;
    int d;
    if (g_is64) d = (int)((const long long*)buf)[e + E];
    else        d = ((const int*)buf)[e + E];
    atomicAdd(&g_cnt[d], 1);
}

// ---------------- K: CSR prefix sum (3 steps) -------------------------------
__global__ void k_scanA() {
    __shared__ int sh[256];
    int i = blockIdx.x * 256 + threadIdx.x;
    sh[threadIdx.x] = (i < NN) ? g_cnt[i] : 0;
    __syncthreads();
    for (int s = 128; s; s >>= 1) {
        if (threadIdx.x < s) sh[threadIdx.x] += sh[threadIdx.x + s];
        __syncthreads();
    }
    if (threadIdx.x == 0) g_bsum[blockIdx.x] = sh[0];
}
__global__ void k_scanB(int nb) {
    __shared__ int sh[512];
    int t = threadIdx.x;
    int v = (t < nb) ? g_bsum[t] : 0;
    sh[t] = v;
    __syncthreads();
    for (int off = 1; off < 512; off <<= 1) {
        int a = (t >= off) ? sh[t - off] : 0;
        __syncthreads();
        sh[t] += a;
        __syncthreads();
    }
    if (t < nb) g_bsum[t] = sh[t] - v;   // exclusive
}
__global__ void k_scanC() {
    __shared__ int sh[256];
    int i = blockIdx.x * 256 + threadIdx.x;
    int t = threadIdx.x;
    int v = (i < NN) ? g_cnt[i] : 0;
    sh[t] = v;
    __syncthreads();
    for (int off = 1; off < 256; off <<= 1) {
        int a = (t >= off) ? sh[t - off] : 0;
        __syncthreads();
        sh[t] += a;
        __syncthreads();
    }
    if (i < NN) g_start[i] = sh[t] - v + g_bsum[blockIdx.x];
}

// ---------------- K: fill CSR (decode both in place; L2-hit re-read) --------
__global__ void k_fill(const void* __restrict__ buf, int E) {
    int e = blockIdx.x * blockDim.x + threadIdx.x;
    if (e >= E) return;
    int s, d;
    if (g_is64) {
        const long long* p = (const long long*)buf;
        s = (int)p[e]; d = (int)p[e + E];
    } else {
        const int* p = (const int*)buf;
        s = p[e]; d = p[e + E];
    }
    int pos = atomicAdd(&g_cursor[d], 1);
    g_csr[g_start[d] + pos] = s;
}

// ---------------- K: h1s = (x @ W1) * dinv ----------------------------------
// 2 threads per row, k-range split in half; 256 threads = 128 rows/block.
// No early return (full-warp shuffle); tail rows clamp loads, predicate store.
// Halves combined with PACKED FLOAT add (add.rn.f32x2), not integer add.
__global__ void __launch_bounds__(256) k_gemm1(const float* __restrict__ x,
                                               const float* __restrict__ W1) {
    __shared__ ulonglong2 wp[FD / 2][HD / 2];   // 32KB: k-pair packed W1
    int t = threadIdx.x;
    for (int i = t; i < (FD / 2) * (HD / 2); i += 256) {
        int k2 = i / (HD / 2);
        int c2 = i % (HD / 2);
        ulonglong2 v;
        v.x = pk2(W1[(2 * k2) * HD + 2 * c2],     W1[(2 * k2 + 1) * HD + 2 * c2]);
        v.y = pk2(W1[(2 * k2) * HD + 2 * c2 + 1], W1[(2 * k2 + 1) * HD + 2 * c2 + 1]);
        wp[k2][c2] = v;
    }
    __syncthreads();

    int r    = blockIdx.x * 128 + (t >> 1);
    int half = t & 1;
    int rc   = (r < NN) ? r : (NN - 1);   // clamped row for loads (dup read ok)

    const ulonglong2* xr = (const ulonglong2*)(x + (size_t)rc * FD) + half * 64;

    unsigned long long acc[HD];
#pragma unroll
    for (int c = 0; c < HD; c++) acc[c] = 0ull;

    // 8 iters x 8 loads (128B per iter) -> MLP 8
    for (int it = 0; it < 8; ++it) {
        ulonglong2 a[8];
#pragma unroll
        for (int m = 0; m < 8; m++) a[m] = __ldg(xr + 8 * it + m);
#pragma unroll
        for (int m = 0; m < 8; m++) {
            int k2 = 2 * (half * 64 + it * 8 + m);
#pragma unroll
            for (int c2 = 0; c2 < HD / 2; c2++) {
                ulonglong2 wv = wp[k2][c2];
                fma2(acc[2 * c2 + 0], a[m].x, wv.x);
                fma2(acc[2 * c2 + 1], a[m].x, wv.y);
            }
#pragma unroll
            for (int c2 = 0; c2 < HD / 2; c2++) {
                ulonglong2 wv = wp[k2 + 1][c2];
                fma2(acc[2 * c2 + 0], a[m].y, wv.x);
                fma2(acc[2 * c2 + 1], a[m].y, wv.y);
            }
        }
    }

    // combine the two k-halves (partner = lane^1): packed FLOAT add
#pragma unroll
    for (int c = 0; c < HD; c++) {
        unsigned long long other = __shfl_xor_sync(0xffffffffu, acc[c], 1);
        add2(acc[c], other);
    }

    if (half == 0 && r < NN) {
        float dv = rsqrtf((float)g_cnt[r] + 1.0f);
        g_dinv[r] = dv;
        float4* h1 = g_h1s + r * 4;
#pragma unroll
        for (int q = 0; q < 4; q++)
            h1[q] = make_float4(unpk_sum(acc[4 * q + 0]) * dv,
                                unpk_sum(acc[4 * q + 1]) * dv,
                                unpk_sum(acc[4 * q + 2]) * dv,
                                unpk_sum(acc[4 * q + 3]) * dv);
    }
}

// ---------------- K: gather layer 1 + fused mid -----------------------------
__global__ void __launch_bounds__(256) k_gather1(const float* __restrict__ b1) {
    int gw   = (blockIdx.x * 256 + threadIdx.x) >> 5;   // node
    int lane = threadIdx.x & 31;
    if (gw >= NN) return;
    int q = lane & 3, n = lane >> 2;
    int beg = g_start[gw], cnt = g_cnt[gw];

    float4 acc = make_float4(0.f, 0.f, 0.f, 0.f);
    for (int i = n; i < cnt; i += 8) {
        int s = __ldg(g_csr + beg + i);
        float4 h = __ldg(g_h1s + s * 4 + q);
        acc.x += h.x; acc.y += h.y; acc.z += h.z; acc.w += h.w;
    }
#pragma unroll
    for (int off = 16; off >= 4; off >>= 1) {
        acc.x += __shfl_xor_sync(0xffffffffu, acc.x, off);
        acc.y += __shfl_xor_sync(0xffffffffu, acc.y, off);
        acc.z += __shfl_xor_sync(0xffffffffu, acc.z, off);
        acc.w += __shfl_xor_sync(0xffffffffu, acc.w, off);
    }
    if (lane < 4) {
        float4 self = g_h1s[gw * 4 + q];
        float  dv   = g_dinv[gw];
        float4 bb   = __ldg((const float4*)b1 + q);
        float4 o;
        o.x = fmaxf(fmaf(acc.x + self.x, dv, bb.x), 0.f) * dv;
        o.y = fmaxf(fmaf(acc.y + self.y, dv, bb.y), 0.f) * dv;
        o.z = fmaxf(fmaf(acc.z + self.z, dv, bb.z), 0.f) * dv;
        o.w = fmaxf(fmaf(acc.w + self.w, dv, bb.w), 0.f) * dv;
        g_ts[gw * 4 + q] = o;
    }
}

// ---------------- K: gather layer 2 -----------------------------------------
__global__ void __launch_bounds__(256) k_gather2() {
    int gw   = (blockIdx.x * 256 + threadIdx.x) >> 5;
    int lane = threadIdx.x & 31;
    if (gw >= NN) return;
    int q = lane & 3, n = lane >> 2;
    int beg = g_start[gw], cnt = g_cnt[gw];

    float4 acc = make_float4(0.f, 0.f, 0.f, 0.f);
    for (int i = n; i < cnt; i += 8) {
        int s = __ldg(g_csr + beg + i);
        float4 h = __ldg(g_ts + s * 4 + q);
        acc.x += h.x; acc.y += h.y; acc.z += h.z; acc.w += h.w;
    }
#pragma unroll
    for (int off = 16; off >= 4; off >>= 1) {
        acc.x += __shfl_xor_sync(0xffffffffu, acc.x, off);
        acc.y += __shfl_xor_sync(0xffffffffu, acc.y, off);
        acc.z += __shfl_xor_sync(0xffffffffu, acc.z, off);
        acc.w += __shfl_xor_sync(0xffffffffu, acc.w, off);
    }
    if (lane < 4) {
        float4 self = g_ts[gw * 4 + q];
        g_acc2[gw * 4 + q] = make_float4(acc.x + self.x, acc.y + self.y,
                                         acc.z + self.z, acc.w + self.w);
    }
}

// ---------------- K: logits = (dinv*acc2)@W2 + b2 ; log_softmax -------------
__global__ void __launch_bounds__(256) k_final(const float* __restrict__ W2,
                                               const float* __restrict__ b2,
                                               float* __restrict__ out,
                                               int write_logits) {
    __shared__ float4 w2s[HD][CD / 4];
    __shared__ float  b2s[CD];
    int t = threadIdx.x;
    for (int i = t; i < HD * (CD / 4); i += 256) {
        int k = i / (CD / 4);
        int j = i % (CD / 4);
        w2s[k][j] = __ldg((const float4*)(W2 + k * CD) + j);
    }
    if (t < CD) b2s[t] = b2[t];
    __syncthreads();

    int r = blockIdx.x * 256 + t;
    if (r >= NN) return;

    float dv = g_dinv[r];
    const float4* a2 = g_acc2 + r * 4;
    float z[HD];
#pragma unroll
    for (int qq = 0; qq < 4; qq++) {
        float4 v = a2[qq];
        z[4 * qq + 0] = v.x * dv;
        z[4 * qq + 1] = v.y * dv;
        z[4 * qq + 2] = v.z * dv;
        z[4 * qq + 3] = v.w * dv;
    }

    float l[CD];
#pragma unroll
    for (int c = 0; c < CD; c++) l[c] = b2s[c];
#pragma unroll
    for (int k = 0; k < HD; k++) {
        float zv = z[k];
#pragma unroll
        for (int j = 0; j < CD / 4; j++) {
            float4 w = w2s[k][j];
            l[4 * j + 0] = fmaf(zv, w.x, l[4 * j + 0]);
            l[4 * j + 1] = fmaf(zv, w.y, l[4 * j + 1]);
            l[4 * j + 2] = fmaf(zv, w.z, l[4 * j + 2]);
            l[4 * j + 3] = fmaf(zv, w.w, l[4 * j + 3]);
        }
    }

    float m = -1e30f;
#pragma unroll
    for (int c = 0; c < CD; c++) m = fmaxf(m, l[c]);
    float sum = 0.0f;
#pragma unroll
    for (int c = 0; c < CD; c++) sum += expf(l[c] - m);
    float lse = m + logf(sum);

    float4* o1 = (float4*)(out + (size_t)r * CD);
#pragma unroll
    for (int j = 0; j < CD / 4; j++)
        o1[j] = make_float4(l[4 * j + 0] - lse, l[4 * j + 1] - lse,
                            l[4 * j + 2] - lse, l[4 * j + 3] - lse);
    if (write_logits) {
        float4* o2 = (float4*)(out + (size_t)NN * CD + (size_t)r * CD);
#pragma unroll
        for (int j = 0; j < CD / 4; j++)
            o2[j] = make_float4(l[4 * j + 0], l[4 * j + 1],
                                l[4 * j + 2], l[4 * j + 3]);
    }
}

// ---------------- host ------------------------------------------------------
extern "C" void kernel_launch(void* const* d_in, const int* in_sizes, int n_in,
                              void* d_out, int out_size) {
    const float* x   = (const float*)d_in[0];
    const void*  ei  = (const void*)d_in[1];
    const float* W1  = (const float*)d_in[2];
    const float* b1  = (const float*)d_in[3];
    const float* W2  = (const float*)d_in[4];
    const float* b2  = (const float*)d_in[5];
    float*       out = (float*)d_out;

    int E = in_sizes[1] / 2;
    if (E > EMAX) E = EMAX;

    int write_logits = (out_size >= 2 * NN * CD) ? 1 : 0;
    int nb_edge   = (E + 255) / 256;
    int nb_gather = (NN * 32 + 255) / 256;   // warp per node
    int nb_gemm   = (NN + 127) / 128;        // 128 rows/block, 256 threads

    k_detect<<<1, 32>>>((const int*)ei);
    k_init<<<NB_NODE, 256>>>();
    k_count<<<nb_edge, 256>>>(ei, E);
    k_scanA<<<NB_NODE, 256>>>();
    k_scanB<<<1, 512>>>(NB_NODE);
    k_scanC<<<NB_NODE, 256>>>();
    k_fill<<<nb_edge, 256>>>(ei, E);
    k_gemm1<<<nb_gemm, 256>>>(x, W1);
    k_gather1<<<nb_gather, 256>>>(b1);
    k_gather2<<<nb_gather, 256>>>();
    k_final<<<NB_NODE, 256>>>(W2, b2, out, write_logits);
}

// round 17
// speedup vs baseline: 1.1408x; 1.1408x over previous
#include <cuda_runtime.h>
#include <math.h>

#define NN 100000
#define FD 512
#define HD 16
#define CD 40
#define EMAX 3400000
#define NB_NODE 391   // ceil(NN/256)

// ---------------- scratch (device globals; no allocation allowed) ----------
__device__ int g_is64;
__device__ __align__(16) int    g_cnt   [NN];     // in-degree (excl self)
__device__ __align__(16) int    g_start [NN];     // CSR row start
__device__ __align__(16) int    g_cursor[NN];
__device__ __align__(16) int    g_bsum  [512];
__device__ __align__(16) int    g_csr [EMAX];     // src ids grouped by dst
__device__ __align__(16) float  g_dinv[NN];
__device__ __align__(16) float4 g_h1s [NN * 4];   // (x@W1)*dinv
__device__ __align__(16) float4 g_ts  [NN * 4];   // relu(out1)*dinv
__device__ __align__(16) float4 g_acc2[NN * 4];   // layer-2 aggregate (raw)

// packed fp32x2 helpers (Blackwell f32x2 — PTX only)
__device__ __forceinline__ unsigned long long pk2(float a, float b) {
    unsigned long long r;
    asm("mov.b64 %0, {%1, %2};" : "=l"(r) : "f"(a), "f"(b));
    return r;
}
__device__ __forceinline__ void fma2(unsigned long long& d,
                                     unsigned long long a, unsigned long long b) {
    asm("fma.rn.f32x2 %0, %1, %2, %0;" : "+l"(d) : "l"(a), "l"(b));
}
__device__ __forceinline__ void add2(unsigned long long& d, unsigned long long a) {
    asm("add.rn.f32x2 %0, %0, %1;" : "+l"(d) : "l"(a));
}
__device__ __forceinline__ float unpk_sum(unsigned long long v) {
    float lo, hi;
    asm("mov.b64 {%0, %1}, %2;" : "=f"(lo), "=f"(hi) : "l"(v));
    return lo + hi;
}

// ---------------- K: detect edge dtype (block 0) + zero counters ------------
__global__ void k_detect_init(const int* __restrict__ buf) {
    int i = blockIdx.x * blockDim.x + threadIdx.x;
    if (i < NN) { g_cnt[i] = 0; g_cursor[i] = 0; }
    if (blockIdx.x == 0 && threadIdx.x < 32) {
        int nz = 0;
        for (int k = threadIdx.x; k < 256; k += 32) nz |= buf[2 * k + 1];
#pragma unroll
        for (int o = 16; o; o >>= 1) nz |= __shfl_xor_sync(0xffffffffu, nz, o);
        if (threadIdx.x == 0) g_is64 = (nz == 0) ? 1 : 0;
    }
}

// ---------------- K: degree histogram (decode dst in place) -----------------
__global__ void k_count(const void* __restrict__ buf, int E) {
    int e = blockIdx.x * blockDim.x + threadIdx.x;
    if (e >= E) return;
    int d;
    if (g_is64) d = (int)((const long long*)buf)[e + E];
    else        d = ((const int*)buf)[e + E];
    atomicAdd(&g_cnt[d], 1);
}

// ---------------- K: CSR prefix sum (3 steps) -------------------------------
__global__ void k_scanA() {
    __shared__ int sh[256];
    int i = blockIdx.x * 256 + threadIdx.x;
    sh[threadIdx.x] = (i < NN) ? g_cnt[i] : 0;
    __syncthreads();
    for (int s = 128; s; s >>= 1) {
        if (threadIdx.x < s) sh[threadIdx.x] += sh[threadIdx.x + s];
        __syncthreads();
    }
    if (threadIdx.x == 0) g_bsum[blockIdx.x] = sh[0];
}
__global__ void k_scanB(int nb) {
    __shared__ int sh[512];
    int t = threadIdx.x;
    int v = (t < nb) ? g_bsum[t] : 0;
    sh[t] = v;
    __syncthreads();
    for (int off = 1; off < 512; off <<= 1) {
        int a = (t >= off) ? sh[t - off] : 0;
        __syncthreads();
        sh[t] += a;
        __syncthreads();
    }
    if (t < nb) g_bsum[t] = sh[t] - v;   // exclusive
}
__global__ void k_scanC() {
    __shared__ int sh[256];
    int i = blockIdx.x * 256 + threadIdx.x;
    int t = threadIdx.x;
    int v = (i < NN) ? g_cnt[i] : 0;
    sh[t] = v;
    __syncthreads();
    for (int off = 1; off < 256; off <<= 1) {
        int a = (t >= off) ? sh[t - off] : 0;
        __syncthreads();
        sh[t] += a;
        __syncthreads();
    }
    if (i < NN) g_start[i] = sh[t] - v + g_bsum[blockIdx.x];
}

// ---------------- K: fill CSR (decode both in place; L2-hit re-read) --------
__global__ void k_fill(const void* __restrict__ buf, int E) {
    int e = blockIdx.x * blockDim.x + threadIdx.x;
    if (e >= E) return;
    int s, d;
    if (g_is64) {
        const long long* p = (const long long*)buf;
        s = (int)p[e]; d = (int)p[e + E];
    } else {
        const int* p = (const int*)buf;
        s = p[e]; d = p[e + E];
    }
    int pos = atomicAdd(&g_cursor[d], 1);
    g_csr[g_start[d] + pos] = s;
}

// ---------------- K: h1s = (x @ W1) * dinv ----------------------------------
// Warp-coherent split-k: warps 0-3 handle k[0:256) of rows 0..127,
// warps 4-7 handle k[256:512) of the SAME rows. All lanes of a warp share
// the same k index -> smem W loads stay warp-broadcast (R6 property),
// but 2x warps cover each row-set -> 2x latency hiding.
// Halves combined via smem staging + packed-float add (no shuffles).
__global__ void __launch_bounds__(256) k_gemm1(const float* __restrict__ x,
                                               const float* __restrict__ W1) {
    __shared__ ulonglong2 wp[FD / 2][HD / 2];          // 32KB: k-pair packed W1
    __shared__ unsigned long long part[128][HD];       // 16KB: half-1 partials
    int t = threadIdx.x;
    for (int i = t; i < (FD / 2) * (HD / 2); i += 256) {
        int k2 = i / (HD / 2);
        int c2 = i % (HD / 2);
        ulonglong2 v;
        v.x = pk2(W1[(2 * k2) * HD + 2 * c2],     W1[(2 * k2 + 1) * HD + 2 * c2]);
        v.y = pk2(W1[(2 * k2) * HD + 2 * c2 + 1], W1[(2 * k2 + 1) * HD + 2 * c2 + 1]);
        wp[k2][c2] = v;
    }
    __syncthreads();

    int half = t >> 7;               // warps 0-3: 0, warps 4-7: 1
    int rl   = t & 127;              // local row
    int r    = blockIdx.x * 128 + rl;
    int rc   = (r < NN) ? r : (NN - 1);   // clamp loads on tail (dup read ok)

    const ulonglong2* xr = (const ulonglong2*)(x + (size_t)rc * FD) + half * 64;

    unsigned long long acc[HD];
#pragma unroll
    for (int c = 0; c < HD; c++) acc[c] = 0ull;

    // 8 iters x 8 loads (128B per iter) -> MLP 8
    for (int it = 0; it < 8; ++it) {
        ulonglong2 a[8];
#pragma unroll
        for (int m = 0; m < 8; m++) a[m] = __ldg(xr + 8 * it + m);
#pragma unroll
        for (int m = 0; m < 8; m++) {
            int k2 = 2 * (half * 64 + it * 8 + m);   // warp-uniform -> broadcast
#pragma unroll
            for (int c2 = 0; c2 < HD / 2; c2++) {
                ulonglong2 wv = wp[k2][c2];
                fma2(acc[2 * c2 + 0], a[m].x, wv.x);
                fma2(acc[2 * c2 + 1], a[m].x, wv.y);
            }
#pragma unroll
            for (int c2 = 0; c2 < HD / 2; c2++) {
                ulonglong2 wv = wp[k2 + 1][c2];
                fma2(acc[2 * c2 + 0], a[m].y, wv.x);
                fma2(acc[2 * c2 + 1], a[m].y, wv.y);
            }
        }
    }

    // half 1 stages its partials; half 0 combines with packed-float add
    if (half == 1) {
#pragma unroll
        for (int c = 0; c < HD; c++) part[rl][c] = acc[c];
    }
    __syncthreads();

    if (half == 0 && r < NN) {
#pragma unroll
        for (int c = 0; c < HD; c++) add2(acc[c], part[rl][c]);

        float dv = rsqrtf((float)g_cnt[r] + 1.0f);
        g_dinv[r] = dv;
        float4* h1 = g_h1s + r * 4;
#pragma unroll
        for (int q = 0; q < 4; q++)
            h1[q] = make_float4(unpk_sum(acc[4 * q + 0]) * dv,
                                unpk_sum(acc[4 * q + 1]) * dv,
                                unpk_sum(acc[4 * q + 2]) * dv,
                                unpk_sum(acc[4 * q + 3]) * dv);
    }
}

// ---------------- K: gather layer 1 + fused mid -----------------------------
__global__ void __launch_bounds__(256) k_gather1(const float* __restrict__ b1) {
    int gw   = (blockIdx.x * 256 + threadIdx.x) >> 5;   // node
    int lane = threadIdx.x & 31;
    if (gw >= NN) return;
    int q = lane & 3, n = lane >> 2;
    int beg = g_start[gw], cnt = g_cnt[gw];

    float4 acc = make_float4(0.f, 0.f, 0.f, 0.f);
    for (int i = n; i < cnt; i += 8) {
        int s = __ldg(g_csr + beg + i);
        float4 h = __ldg(g_h1s + s * 4 + q);
        acc.x += h.x; acc.y += h.y; acc.z += h.z; acc.w += h.w;
    }
#pragma unroll
    for (int off = 16; off >= 4; off >>= 1) {
        acc.x += __shfl_xor_sync(0xffffffffu, acc.x, off);
        acc.y += __shfl_xor_sync(0xffffffffu, acc.y, off);
        acc.z += __shfl_xor_sync(0xffffffffu, acc.z, off);
        acc.w += __shfl_xor_sync(0xffffffffu, acc.w, off);
    }
    if (lane < 4) {
        float4 self = g_h1s[gw * 4 + q];
        float  dv   = g_dinv[gw];
        float4 bb   = __ldg((const float4*)b1 + q);
        float4 o;
        o.x = fmaxf(fmaf(acc.x + self.x, dv, bb.x), 0.f) * dv;
        o.y = fmaxf(fmaf(acc.y + self.y, dv, bb.y), 0.f) * dv;
        o.z = fmaxf(fmaf(acc.z + self.z, dv, bb.z), 0.f) * dv;
        o.w = fmaxf(fmaf(acc.w + self.w, dv, bb.w), 0.f) * dv;
        g_ts[gw * 4 + q] = o;
    }
}

// ---------------- K: gather layer 2 -----------------------------------------
__global__ void __launch_bounds__(256) k_gather2() {
    int gw   = (blockIdx.x * 256 + threadIdx.x) >> 5;
    int lane = threadIdx.x & 31;
    if (gw >= NN) return;
    int q = lane & 3, n = lane >> 2;
    int beg = g_start[gw], cnt = g_cnt[gw];

    float4 acc = make_float4(0.f, 0.f, 0.f, 0.f);
    for (int i = n; i < cnt; i += 8) {
        int s = __ldg(g_csr + beg + i);
        float4 h = __ldg(g_ts + s * 4 + q);
        acc.x += h.x; acc.y += h.y; acc.z += h.z; acc.w += h.w;
    }
#pragma unroll
    for (int off = 16; off >= 4; off >>= 1) {
        acc.x += __shfl_xor_sync(0xffffffffu, acc.x, off);
        acc.y += __shfl_xor_sync(0xffffffffu, acc.y, off);
        acc.z += __shfl_xor_sync(0xffffffffu, acc.z, off);
        acc.w += __shfl_xor_sync(0xffffffffu, acc.w, off);
    }
    if (lane < 4) {
        float4 self = g_ts[gw * 4 + q];
        g_acc2[gw * 4 + q] = make_float4(acc.x + self.x, acc.y + self.y,
                                         acc.z + self.z, acc.w + self.w);
    }
}

// ---------------- K: logits = (dinv*acc2)@W2 + b2 ; log_softmax -------------
__global__ void __launch_bounds__(256) k_final(const float* __restrict__ W2,
                                               const float* __restrict__ b2,
                                               float* __restrict__ out,
                                               int write_logits) {
    __shared__ float4 w2s[HD][CD / 4];
    __shared__ float  b2s[CD];
    int t = threadIdx.x;
    for (int i = t; i < HD * (CD / 4); i += 256) {
        int k = i / (CD / 4);
        int j = i % (CD / 4);
        w2s[k][j] = __ldg((const float4*)(W2 + k * CD) + j);
    }
    if (t < CD) b2s[t] = b2[t];
    __syncthreads();

    int r = blockIdx.x * 256 + t;
    if (r >= NN) return;

    float dv = g_dinv[r];
    const float4* a2 = g_acc2 + r * 4;
    float z[HD];
#pragma unroll
    for (int qq = 0; qq < 4; qq++) {
        float4 v = a2[qq];
        z[4 * qq + 0] = v.x * dv;
        z[4 * qq + 1] = v.y * dv;
        z[4 * qq + 2] = v.z * dv;
        z[4 * qq + 3] = v.w * dv;
    }

    float l[CD];
#pragma unroll
    for (int c = 0; c < CD; c++) l[c] = b2s[c];
#pragma unroll
    for (int k = 0; k < HD; k++) {
        float zv = z[k];
#pragma unroll
        for (int j = 0; j < CD / 4; j++) {
            float4 w = w2s[k][j];
            l[4 * j + 0] = fmaf(zv, w.x, l[4 * j + 0]);
            l[4 * j + 1] = fmaf(zv, w.y, l[4 * j + 1]);
            l[4 * j + 2] = fmaf(zv, w.z, l[4 * j + 2]);
            l[4 * j + 3] = fmaf(zv, w.w, l[4 * j + 3]);
        }
    }

    float m = -1e30f;
#pragma unroll
    for (int c = 0; c < CD; c++) m = fmaxf(m, l[c]);
    float sum = 0.0f;
#pragma unroll
    for (int c = 0; c < CD; c++) sum += expf(l[c] - m);
    float lse = m + logf(sum);

    float4* o1 = (float4*)(out + (size_t)r * CD);
#pragma unroll
    for (int j = 0; j < CD / 4; j++)
        o1[j] = make_float4(l[4 * j + 0] - lse, l[4 * j + 1] - lse,
                            l[4 * j + 2] - lse, l[4 * j + 3] - lse);
    if (write_logits) {
        float4* o2 = (float4*)(out + (size_t)NN * CD + (size_t)r * CD);
#pragma unroll
        for (int j = 0; j < CD / 4; j++)
            o2[j] = make_float4(l[4 * j + 0], l[4 * j + 1],
                                l[4 * j + 2], l[4 * j + 3]);
    }
}

// ---------------- host ------------------------------------------------------
extern "C" void kernel_launch(void* const* d_in, const int* in_sizes, int n_in,
                              void* d_out, int out_size) {
    const float* x   = (const float*)d_in[0];
    const void*  ei  = (const void*)d_in[1];
    const float* W1  = (const float*)d_in[2];
    const float* b1  = (const float*)d_in[3];
    const float* W2  = (const float*)d_in[4];
    const float* b2  = (const float*)d_in[5];
    float*       out = (float*)d_out;

    int E = in_sizes[1] / 2;
    if (E > EMAX) E = EMAX;

    int write_logits = (out_size >= 2 * NN * CD) ? 1 : 0;
    int nb_edge   = (E + 255) / 256;
    int nb_gather = (NN * 32 + 255) / 256;   // warp per node
    int nb_gemm   = (NN + 127) / 128;        // 128 rows/block, 256 threads

    k_detect_init<<<NB_NODE, 256>>>((const int*)ei);
    k_count<<<nb_edge, 256>>>(ei, E);
    k_scanA<<<NB_NODE, 256>>>();
    k_scanB<<<1, 512>>>(NB_NODE);
    k_scanC<<<NB_NODE, 256>>>();
    k_fill<<<nb_edge, 256>>>(ei, E);
    k_gemm1<<<nb_gemm, 256>>>(x, W1);
    k_gather1<<<nb_gather, 256>>>(b1);
    k_gather2<<<nb_gather, 256>>>();
    k_final<<<NB_NODE, 256>>>(W2, b2, out, write_logits);
}